// round 5
// baseline (speedup 1.0000x reference)
#include <cuda_runtime.h>
#include <cstdint>

#define NN   100000
#define NE   3200000
#define INF  1433
#define HID  16
#define OUTF 7

// ---- scratch (device globals: allocation-free) ----
__device__ int   g_idx64;              // 1 if edge_index is int64, 0 if int32
__device__ int   g_idx[2 * NE];        // densified edge indices: [src | dst]
__device__ float g_deg_out[NN];
__device__ float g_deg_in[NN];
__device__ float g_ns[NN];
__device__ float g_nd[NN];
__device__ float g_x1[(size_t)NN * HID];   // (feat*ns)@W1, per-node
__device__ float g_m1[(size_t)NN * HID];   // scatter accum layer 1
__device__ float g_x2[(size_t)NN * 8];     // (relu(h)*ns)@W2, padded to 8
__device__ float g_m2[(size_t)NN * 8];     // scatter accum layer 2

// ---------------------------------------------------------------------------
// K_detect: decide whether edge_index is int64 or int32.
// If int64 with values < 2^31, every odd 32-bit word (high half) is 0.
// If int32, odd words are random node ids (all-zero probability ~0).
// ---------------------------------------------------------------------------
__global__ void k_detect(const unsigned int* __restrict__ ei_words) {
    __shared__ unsigned int acc;
    if (threadIdx.x == 0) acc = 0u;
    __syncthreads();
    unsigned int v = ei_words[2 * threadIdx.x + 1];   // odd words 1,3,...,63
    atomicOr(&acc, v);
    __syncthreads();
    if (threadIdx.x == 0) g_idx64 = (acc == 0u) ? 1 : 0;
}

// ---------------------------------------------------------------------------
// K_convert: densify indices to int32 (handles both source dtypes)
// ---------------------------------------------------------------------------
__global__ void k_convert(const void* __restrict__ ei) {
    int i = blockIdx.x * blockDim.x + threadIdx.x;
    if (i >= 2 * NE) return;
    if (g_idx64) g_idx[i] = (int)((const long long*)ei)[i];
    else         g_idx[i] = ((const int*)ei)[i];
}

// ---------------------------------------------------------------------------
// K0: zero the accumulators + degree arrays
// ---------------------------------------------------------------------------
__global__ void k_zero() {
    int i = blockIdx.x * blockDim.x + threadIdx.x;
    int stride = gridDim.x * blockDim.x;
    for (int j = i; j < NN; j += stride) { g_deg_out[j] = 0.f; g_deg_in[j] = 0.f; }
    for (int j = i; j < NN * HID; j += stride) g_m1[j] = 0.f;
    for (int j = i; j < NN * 8;   j += stride) g_m2[j] = 0.f;
}

// ---------------------------------------------------------------------------
// K1: degrees via no-return float atomics (REDG)
// ---------------------------------------------------------------------------
__global__ void k_deg() {
    int e = blockIdx.x * blockDim.x + threadIdx.x;
    if (e >= NE) return;
    atomicAdd(&g_deg_out[g_idx[e]], 1.0f);
    atomicAdd(&g_deg_in[g_idx[NE + e]], 1.0f);
}

// ---------------------------------------------------------------------------
// K2: norms = rsqrt(max(deg,1))
// ---------------------------------------------------------------------------
__global__ void k_norm() {
    int i = blockIdx.x * blockDim.x + threadIdx.x;
    if (i >= NN) return;
    g_ns[i] = rsqrtf(fmaxf(g_deg_out[i], 1.0f));
    g_nd[i] = rsqrtf(fmaxf(g_deg_in[i], 1.0f));
}

// ---------------------------------------------------------------------------
// K3: x1 = (feat * ns[:,None]) @ W1     [NN,1433] x [1433,16]
// warp handles 32 rows; feature tile [32][32] staged in smem (pad 33);
// lane = row; W1 row loads are lane-uniform (1 sector, L1-resident).
// ns applied to the final accumulators (scaling commutes with the dot product).
// ---------------------------------------------------------------------------
__global__ void __launch_bounds__(256) k_gemm1(const float* __restrict__ feat,
                                               const float* __restrict__ W1) {
    __shared__ float tile[8][32][33];
    const int warp = threadIdx.x >> 5;
    const int lane = threadIdx.x & 31;
    const int r0 = (blockIdx.x * 8 + warp) * 32;
    if (r0 >= NN) return;   // uniform per warp

    float acc[16];
#pragma unroll
    for (int j = 0; j < 16; j++) acc[j] = 0.f;

    float (*t)[33] = tile[warp];

    for (int k0 = 0; k0 < INF; k0 += 32) {
        const int k = k0 + lane;
        const bool kok = (k < INF);
        // load tile: t[row][col], coalesced 128B per row
#pragma unroll 8
        for (int rr = 0; rr < 32; rr++) {
            const int r = r0 + rr;
            t[rr][lane] = (kok && r < NN) ? feat[(size_t)r * INF + k] : 0.f;
        }
        __syncwarp();

#pragma unroll 8
        for (int kk = 0; kk < 32; kk++) {
            const int k2 = k0 + kk;
            const float f = t[lane][kk];       // conflict-free: bank=(lane+kk)%32
            if (k2 < INF) {                    // warp-uniform branch
                const float4* w = (const float4*)(W1 + (size_t)k2 * 16);
                const float4 w0 = __ldg(w + 0);
                const float4 w1 = __ldg(w + 1);
                const float4 w2 = __ldg(w + 2);
                const float4 w3 = __ldg(w + 3);
                acc[0]  += f * w0.x; acc[1]  += f * w0.y; acc[2]  += f * w0.z; acc[3]  += f * w0.w;
                acc[4]  += f * w1.x; acc[5]  += f * w1.y; acc[6]  += f * w1.z; acc[7]  += f * w1.w;
                acc[8]  += f * w2.x; acc[9]  += f * w2.y; acc[10] += f * w2.z; acc[11] += f * w2.w;
                acc[12] += f * w3.x; acc[13] += f * w3.y; acc[14] += f * w3.z; acc[15] += f * w3.w;
            }
        }
        __syncwarp();
    }

    const int myrow = r0 + lane;
    if (myrow < NN) {
        const float s = g_ns[myrow];
        float4* o = (float4*)(g_x1 + (size_t)myrow * 16);
        o[0] = make_float4(acc[0] * s,  acc[1] * s,  acc[2] * s,  acc[3] * s);
        o[1] = make_float4(acc[4] * s,  acc[5] * s,  acc[6] * s,  acc[7] * s);
        o[2] = make_float4(acc[8] * s,  acc[9] * s,  acc[10] * s, acc[11] * s);
        o[3] = make_float4(acc[12] * s, acc[13] * s, acc[14] * s, acc[15] * s);
    }
}

// ---------------------------------------------------------------------------
// K4: m1[dst] += x1[src]   (16 floats/edge, scalar no-return atomics)
// ---------------------------------------------------------------------------
__global__ void k_scatter1() {
    int e = blockIdx.x * blockDim.x + threadIdx.x;
    if (e >= NE) return;
    const int s = g_idx[e];
    const int d = g_idx[NE + e];
    const float4* xs = (const float4*)(g_x1 + (size_t)s * 16);
    float* md = g_m1 + (size_t)d * 16;
#pragma unroll
    for (int c = 0; c < 4; c++) {
        const float4 v = __ldg(xs + c);
        atomicAdd(md + 4 * c + 0, v.x);
        atomicAdd(md + 4 * c + 1, v.y);
        atomicAdd(md + 4 * c + 2, v.z);
        atomicAdd(md + 4 * c + 3, v.w);
    }
}

// ---------------------------------------------------------------------------
// K5: h = relu(m1*nd + b1);  x2 = (h*ns) @ W2   (pad col 7 with zeros)
// ---------------------------------------------------------------------------
__global__ void __launch_bounds__(256) k_layer2(const float* __restrict__ b1,
                                                const float* __restrict__ W2) {
    __shared__ float sW[16 * 7];
    __shared__ float sb1[16];
    const int tid = threadIdx.x;
    if (tid < 112) sW[tid] = W2[tid];
    if (tid < 16)  sb1[tid] = b1[tid];
    __syncthreads();

    const int r = blockIdx.x * blockDim.x + tid;
    if (r >= NN) return;
    const float nd = g_nd[r];
    const float ns = g_ns[r];

    float h[16];
    const float4* m = (const float4*)(g_m1 + (size_t)r * 16);
#pragma unroll
    for (int c = 0; c < 4; c++) {
        const float4 v = m[c];
        h[4 * c + 0] = fmaxf(fmaf(v.x, nd, sb1[4 * c + 0]), 0.f) * ns;
        h[4 * c + 1] = fmaxf(fmaf(v.y, nd, sb1[4 * c + 1]), 0.f) * ns;
        h[4 * c + 2] = fmaxf(fmaf(v.z, nd, sb1[4 * c + 2]), 0.f) * ns;
        h[4 * c + 3] = fmaxf(fmaf(v.w, nd, sb1[4 * c + 3]), 0.f) * ns;
    }

    float* xo = g_x2 + (size_t)r * 8;
#pragma unroll
    for (int j2 = 0; j2 < 7; j2++) {
        float o = 0.f;
#pragma unroll
        for (int j = 0; j < 16; j++) o = fmaf(h[j], sW[j * 7 + j2], o);
        xo[j2] = o;
    }
    xo[7] = 0.f;
}

// ---------------------------------------------------------------------------
// K6: m2[dst] += x2[src]   (8 floats/edge, scalar no-return atomics)
// ---------------------------------------------------------------------------
__global__ void k_scatter2() {
    int e = blockIdx.x * blockDim.x + threadIdx.x;
    if (e >= NE) return;
    const int s = g_idx[e];
    const int d = g_idx[NE + e];
    const float4* xs = (const float4*)(g_x2 + (size_t)s * 8);
    float* md = g_m2 + (size_t)d * 8;
#pragma unroll
    for (int c = 0; c < 2; c++) {
        const float4 v = __ldg(xs + c);
        atomicAdd(md + 4 * c + 0, v.x);
        atomicAdd(md + 4 * c + 1, v.y);
        atomicAdd(md + 4 * c + 2, v.z);
        atomicAdd(md + 4 * c + 3, v.w);
    }
}

// ---------------------------------------------------------------------------
// K7: out = m2[:, :7] * nd + b2
// ---------------------------------------------------------------------------
__global__ void k_out(float* __restrict__ out, const float* __restrict__ b2) {
    int i = blockIdx.x * blockDim.x + threadIdx.x;
    if (i >= NN * OUTF) return;
    const int r = i / OUTF;
    const int j = i - r * OUTF;
    out[i] = fmaf(g_m2[(size_t)r * 8 + j], g_nd[r], b2[j]);
}

// ---------------------------------------------------------------------------
extern "C" void kernel_launch(void* const* d_in, const int* in_sizes, int n_in,
                              void* d_out, int out_size) {
    const float* feat = (const float*)d_in[0];
    const void*  ei   = d_in[1];
    const float* W1   = (const float*)d_in[2];
    const float* b1   = (const float*)d_in[3];
    const float* W2   = (const float*)d_in[4];
    const float* b2   = (const float*)d_in[5];
    float*       out  = (float*)d_out;

    k_detect<<<1, 32>>>((const unsigned int*)ei);
    k_convert<<<(2 * NE + 255) / 256, 256>>>(ei);
    k_zero<<<4096, 256>>>();
    k_deg<<<(NE + 255) / 256, 256>>>();
    k_norm<<<(NN + 255) / 256, 256>>>();
    k_gemm1<<<(NN + 255) / 256, 256>>>(feat, W1);
    k_scatter1<<<(NE + 255) / 256, 256>>>();
    k_layer2<<<(NN + 255) / 256, 256>>>(b1, W2);
    k_scatter2<<<(NE + 255) / 256, 256>>>();
    k_out<<<(NN * OUTF + 255) / 256, 256>>>(out, b2);
}

// round 6
// speedup vs baseline: 1.2859x; 1.2859x over previous
#include <cuda_runtime.h>
#include <cstdint>

#define NN   100000
#define NE   3200000
#define INF  1433
#define HID  16
#define OUTF 7
#define SCAN_BLK 512
#define NSCAN ((NN + SCAN_BLK - 1) / SCAN_BLK)   // 196

// ---- scratch (device globals: allocation-free) ----
__device__ int   g_idx64;               // 1 if edge_index is int64, 0 if int32
__device__ int   g_idx[2 * NE];         // densified edge indices: [src | dst]
__device__ int   g_csr[NE];             // src ids sorted by dst
__device__ int   g_cnt_src[NN];         // out-degree
__device__ int   g_cnt_dst[NN];         // in-degree
__device__ int   g_off[NN];             // CSR row offsets (by dst)
__device__ int   g_cur[NN];             // fill cursors
__device__ int   g_bsum[NSCAN];         // scan block sums
__device__ float g_ns[NN];
__device__ float g_nd[NN];
__device__ float g_x1[(size_t)NN * HID];   // (feat*ns)@W1
__device__ float g_m1[(size_t)NN * HID];   // gathered layer-1 messages
__device__ float g_x2[(size_t)NN * 8];     // (relu(h)*ns)@W2, padded to 8

// ---------------------------------------------------------------------------
// dtype detect: odd 32-bit words all-zero <=> int64 with small values
// ---------------------------------------------------------------------------
__global__ void k_detect(const unsigned int* __restrict__ ei_words) {
    __shared__ unsigned int acc;
    if (threadIdx.x == 0) acc = 0u;
    __syncthreads();
    unsigned int v = ei_words[2 * threadIdx.x + 1];
    atomicOr(&acc, v);
    __syncthreads();
    if (threadIdx.x == 0) g_idx64 = (acc == 0u) ? 1 : 0;
}

__global__ void k_convert(const void* __restrict__ ei) {
    int i = blockIdx.x * blockDim.x + threadIdx.x;
    if (i >= 2 * NE) return;
    if (g_idx64) g_idx[i] = (int)((const long long*)ei)[i];
    else         g_idx[i] = ((const int*)ei)[i];
}

__global__ void k_zero() {
    int i = blockIdx.x * blockDim.x + threadIdx.x;
    if (i < NN) { g_cnt_src[i] = 0; g_cnt_dst[i] = 0; }
}

// ---------------------------------------------------------------------------
// degree counting (int atomics)
// ---------------------------------------------------------------------------
__global__ void k_count() {
    int e = blockIdx.x * blockDim.x + threadIdx.x;
    if (e >= NE) return;
    atomicAdd(&g_cnt_src[g_idx[e]], 1);
    atomicAdd(&g_cnt_dst[g_idx[NE + e]], 1);
}

__global__ void k_norm() {
    int i = blockIdx.x * blockDim.x + threadIdx.x;
    if (i >= NN) return;
    g_ns[i] = rsqrtf(fmaxf((float)g_cnt_src[i], 1.0f));
    g_nd[i] = rsqrtf(fmaxf((float)g_cnt_dst[i], 1.0f));
}

// ---------------------------------------------------------------------------
// exclusive scan of g_cnt_dst -> g_off  (3 kernels)
// ---------------------------------------------------------------------------
__global__ void k_scan1() {
    __shared__ int s[SCAN_BLK];
    int tid = threadIdx.x;
    int i = blockIdx.x * SCAN_BLK + tid;
    int v = (i < NN) ? g_cnt_dst[i] : 0;
    s[tid] = v;
    __syncthreads();
    for (int o = 1; o < SCAN_BLK; o <<= 1) {
        int t = (tid >= o) ? s[tid - o] : 0;
        __syncthreads();
        s[tid] += t;
        __syncthreads();
    }
    if (i < NN) g_off[i] = s[tid] - v;                 // block-local exclusive
    if (tid == SCAN_BLK - 1) g_bsum[blockIdx.x] = s[tid];
}

__global__ void k_scan2() {
    __shared__ int s[SCAN_BLK];
    int tid = threadIdx.x;
    int v = (tid < NSCAN) ? g_bsum[tid] : 0;
    s[tid] = v;
    __syncthreads();
    for (int o = 1; o < SCAN_BLK; o <<= 1) {
        int t = (tid >= o) ? s[tid - o] : 0;
        __syncthreads();
        s[tid] += t;
        __syncthreads();
    }
    if (tid < NSCAN) g_bsum[tid] = s[tid] - v;         // exclusive block sums
}

__global__ void k_scan3() {
    int i = blockIdx.x * SCAN_BLK + threadIdx.x;
    if (i >= NN) return;
    int o = g_off[i] + g_bsum[blockIdx.x];
    g_off[i] = o;
    g_cur[i] = o;
}

// ---------------------------------------------------------------------------
// CSR fill: csr[pos(dst)] = src
// ---------------------------------------------------------------------------
__global__ void k_fill() {
    int e = blockIdx.x * blockDim.x + threadIdx.x;
    if (e >= NE) return;
    int s = g_idx[e];
    int d = g_idx[NE + e];
    int pos = atomicAdd(&g_cur[d], 1);
    g_csr[pos] = s;
}

// ---------------------------------------------------------------------------
// gemm1: x1 = (feat * ns[:,None]) @ W1  via packed f32x2 FFMA
// warp = 32 rows; smem tile 32x32 (pad 33); col-pairs packed into b64.
// NN % 32 == 0 so no row tail.
// ---------------------------------------------------------------------------
__global__ void __launch_bounds__(256) k_gemm1(const float* __restrict__ feat,
                                               const float* __restrict__ W1) {
    __shared__ float tile[8][32][33];
    const int warp = threadIdx.x >> 5;
    const int lane = threadIdx.x & 31;
    const int r0 = (blockIdx.x * 8 + warp) * 32;
    if (r0 >= NN) return;   // uniform per warp

    unsigned long long acc[8];
#pragma unroll
    for (int j = 0; j < 8; j++) acc[j] = 0ULL;   // (0.f, 0.f)

    float (*t)[33] = tile[warp];

    for (int k0 = 0; k0 < INF; k0 += 32) {
        const int k = k0 + lane;
        const bool kok = (k < INF);
#pragma unroll 8
        for (int rr = 0; rr < 32; rr++) {
            t[rr][lane] = kok ? feat[(size_t)(r0 + rr) * INF + k] : 0.f;
        }
        __syncwarp();

#pragma unroll 4
        for (int kk = 0; kk < 32; kk++) {
            const int k2 = k0 + kk;
            if (k2 < INF) {                    // warp-uniform
                const float f = t[lane][kk];   // conflict-free
                unsigned long long ff;
                asm("mov.b64 %0, {%1, %1};" : "=l"(ff) : "f"(f));
                const float* wr = W1 + (size_t)k2 * 16;
                unsigned long long w0, w1, w2, w3, w4, w5, w6, w7;
                asm("ld.global.nc.v2.b64 {%0,%1}, [%2];" : "=l"(w0), "=l"(w1) : "l"(wr));
                asm("ld.global.nc.v2.b64 {%0,%1}, [%2];" : "=l"(w2), "=l"(w3) : "l"(wr + 4));
                asm("ld.global.nc.v2.b64 {%0,%1}, [%2];" : "=l"(w4), "=l"(w5) : "l"(wr + 8));
                asm("ld.global.nc.v2.b64 {%0,%1}, [%2];" : "=l"(w6), "=l"(w7) : "l"(wr + 12));
                asm("fma.rn.f32x2 %0, %1, %2, %0;" : "+l"(acc[0]) : "l"(ff), "l"(w0));
                asm("fma.rn.f32x2 %0, %1, %2, %0;" : "+l"(acc[1]) : "l"(ff), "l"(w1));
                asm("fma.rn.f32x2 %0, %1, %2, %0;" : "+l"(acc[2]) : "l"(ff), "l"(w2));
                asm("fma.rn.f32x2 %0, %1, %2, %0;" : "+l"(acc[3]) : "l"(ff), "l"(w3));
                asm("fma.rn.f32x2 %0, %1, %2, %0;" : "+l"(acc[4]) : "l"(ff), "l"(w4));
                asm("fma.rn.f32x2 %0, %1, %2, %0;" : "+l"(acc[5]) : "l"(ff), "l"(w5));
                asm("fma.rn.f32x2 %0, %1, %2, %0;" : "+l"(acc[6]) : "l"(ff), "l"(w6));
                asm("fma.rn.f32x2 %0, %1, %2, %0;" : "+l"(acc[7]) : "l"(ff), "l"(w7));
            }
        }
        __syncwarp();
    }

    const int myrow = r0 + lane;
    const float s = g_ns[myrow];
    float o[16];
#pragma unroll
    for (int j = 0; j < 8; j++) {
        float lo, hi;
        asm("mov.b64 {%0, %1}, %2;" : "=f"(lo), "=f"(hi) : "l"(acc[j]));
        o[2 * j]     = lo * s;
        o[2 * j + 1] = hi * s;
    }
    float4* op = (float4*)(g_x1 + (size_t)myrow * 16);
#pragma unroll
    for (int c = 0; c < 4; c++)
        op[c] = make_float4(o[4 * c], o[4 * c + 1], o[4 * c + 2], o[4 * c + 3]);
}

// ---------------------------------------------------------------------------
// gather1: m1[n] = sum over incoming edges of x1[src]; 16 lanes per node
// ---------------------------------------------------------------------------
__global__ void __launch_bounds__(256) k_gather1() {
    int t = blockIdx.x * blockDim.x + threadIdx.x;
    int node = t >> 4;
    int j = t & 15;
    if (node >= NN) return;
    int beg = g_off[node];
    int end = beg + g_cnt_dst[node];
    float acc = 0.f;
#pragma unroll 4
    for (int e = beg; e < end; e++) {
        int s = g_csr[e];                          // broadcast across 16 lanes
        acc += g_x1[(size_t)s * 16 + j];
    }
    g_m1[(size_t)node * 16 + j] = acc;
}

// ---------------------------------------------------------------------------
// layer2: h = relu(m1*nd + b1);  x2 = (h*ns) @ W2  (pad col 7 = 0)
// ---------------------------------------------------------------------------
__global__ void __launch_bounds__(256) k_layer2(const float* __restrict__ b1,
                                                const float* __restrict__ W2) {
    __shared__ float sW[16 * 7];
    __shared__ float sb1[16];
    const int tid = threadIdx.x;
    if (tid < 112) sW[tid] = W2[tid];
    if (tid < 16)  sb1[tid] = b1[tid];
    __syncthreads();

    const int r = blockIdx.x * blockDim.x + tid;
    if (r >= NN) return;
    const float nd = g_nd[r];
    const float ns = g_ns[r];

    float h[16];
    const float4* m = (const float4*)(g_m1 + (size_t)r * 16);
#pragma unroll
    for (int c = 0; c < 4; c++) {
        const float4 v = m[c];
        h[4 * c + 0] = fmaxf(fmaf(v.x, nd, sb1[4 * c + 0]), 0.f) * ns;
        h[4 * c + 1] = fmaxf(fmaf(v.y, nd, sb1[4 * c + 1]), 0.f) * ns;
        h[4 * c + 2] = fmaxf(fmaf(v.z, nd, sb1[4 * c + 2]), 0.f) * ns;
        h[4 * c + 3] = fmaxf(fmaf(v.w, nd, sb1[4 * c + 3]), 0.f) * ns;
    }

    float* xo = g_x2 + (size_t)r * 8;
#pragma unroll
    for (int j2 = 0; j2 < 7; j2++) {
        float o = 0.f;
#pragma unroll
        for (int j = 0; j < 16; j++) o = fmaf(h[j], sW[j * 7 + j2], o);
        xo[j2] = o;
    }
    xo[7] = 0.f;
}

// ---------------------------------------------------------------------------
// gather2 + epilogue: out[n,:7] = (sum x2[src]) * nd + b2 ; 8 lanes per node
// ---------------------------------------------------------------------------
__global__ void __launch_bounds__(256) k_gather2(float* __restrict__ out,
                                                 const float* __restrict__ b2) {
    int t = blockIdx.x * blockDim.x + threadIdx.x;
    int node = t >> 3;
    int j = t & 7;
    if (node >= NN) return;
    int beg = g_off[node];
    int end = beg + g_cnt_dst[node];
    float acc = 0.f;
#pragma unroll 4
    for (int e = beg; e < end; e++) {
        int s = g_csr[e];                          // broadcast across 8 lanes
        acc += g_x2[(size_t)s * 8 + j];
    }
    if (j < 7)
        out[(size_t)node * 7 + j] = fmaf(acc, g_nd[node], __ldg(b2 + j));
}

// ---------------------------------------------------------------------------
extern "C" void kernel_launch(void* const* d_in, const int* in_sizes, int n_in,
                              void* d_out, int out_size) {
    const float* feat = (const float*)d_in[0];
    const void*  ei   = d_in[1];
    const float* W1   = (const float*)d_in[2];
    const float* b1   = (const float*)d_in[3];
    const float* W2   = (const float*)d_in[4];
    const float* b2   = (const float*)d_in[5];
    float*       out  = (float*)d_out;

    k_detect<<<1, 32>>>((const unsigned int*)ei);
    k_convert<<<(2 * NE + 255) / 256, 256>>>(ei);
    k_zero<<<(NN + 255) / 256, 256>>>();
    k_count<<<(NE + 255) / 256, 256>>>();
    k_norm<<<(NN + 255) / 256, 256>>>();
    k_scan1<<<NSCAN, SCAN_BLK>>>();
    k_scan2<<<1, SCAN_BLK>>>();
    k_scan3<<<NSCAN, SCAN_BLK>>>();
    k_fill<<<(NE + 255) / 256, 256>>>();
    k_gemm1<<<(NN / 32 + 7) / 8, 256>>>(feat, W1);
    k_gather1<<<(NN * 16 + 255) / 256, 256>>>();
    k_layer2<<<(NN + 255) / 256, 256>>>(b1, W2);
    k_gather2<<<(NN * 8 + 255) / 256, 256>>>(out, b2);
}

// round 8
// speedup vs baseline: 1.8776x; 1.4601x over previous
#include <cuda_runtime.h>
#include <cstdint>

#define NN   100000
#define NE   3200000
#define INF  1433
#define HID  16
#define OUTF 7
#define SCAN_BLK 512
#define NSCAN ((NN + SCAN_BLK - 1) / SCAN_BLK)   // 196

// ---- scratch (device globals: allocation-free) ----
__device__ int   g_idx64;               // 1 if edge_index is int64, 0 if int32
__device__ int   g_idx[2 * NE];         // densified edge indices: [src | dst]
__device__ int   g_csr[NE];             // src ids sorted by dst
__device__ int   g_cnt_src[NN];         // out-degree
__device__ int   g_cnt_dst[NN];         // in-degree
__device__ int   g_off[NN];             // CSR row offsets (by dst)
__device__ int   g_cur[NN];             // fill cursors
__device__ int   g_bsum[NSCAN];         // scan block sums
__device__ float g_ns[NN];
__device__ float g_nd[NN];
__device__ float g_x1[(size_t)NN * HID];   // (feat*ns)@W1
__device__ float g_m1[(size_t)NN * HID];   // gathered layer-1 messages
__device__ float g_x2[(size_t)NN * 8];     // (relu(h)*ns)@W2, padded to 8

// ---------------------------------------------------------------------------
// dtype detect: odd 32-bit words all-zero <=> int64 with small values
// ---------------------------------------------------------------------------
__global__ void k_detect(const unsigned int* __restrict__ ei_words) {
    __shared__ unsigned int acc;
    if (threadIdx.x == 0) acc = 0u;
    __syncthreads();
    unsigned int v = ei_words[2 * threadIdx.x + 1];
    atomicOr(&acc, v);
    __syncthreads();
    if (threadIdx.x == 0) g_idx64 = (acc == 0u) ? 1 : 0;
}

__global__ void k_convert(const void* __restrict__ ei) {
    int i = blockIdx.x * blockDim.x + threadIdx.x;
    if (i >= 2 * NE) return;
    if (g_idx64) g_idx[i] = (int)((const long long*)ei)[i];
    else         g_idx[i] = ((const int*)ei)[i];
}

__global__ void k_zero() {
    int i = blockIdx.x * blockDim.x + threadIdx.x;
    if (i < NN) { g_cnt_src[i] = 0; g_cnt_dst[i] = 0; }
}

// ---------------------------------------------------------------------------
// degree counting (int atomics)
// ---------------------------------------------------------------------------
__global__ void k_count() {
    int e = blockIdx.x * blockDim.x + threadIdx.x;
    if (e >= NE) return;
    atomicAdd(&g_cnt_src[g_idx[e]], 1);
    atomicAdd(&g_cnt_dst[g_idx[NE + e]], 1);
}

__global__ void k_norm() {
    int i = blockIdx.x * blockDim.x + threadIdx.x;
    if (i >= NN) return;
    g_ns[i] = rsqrtf(fmaxf((float)g_cnt_src[i], 1.0f));
    g_nd[i] = rsqrtf(fmaxf((float)g_cnt_dst[i], 1.0f));
}

// ---------------------------------------------------------------------------
// exclusive scan of g_cnt_dst -> g_off  (3 kernels)
// ---------------------------------------------------------------------------
__global__ void k_scan1() {
    __shared__ int s[SCAN_BLK];
    int tid = threadIdx.x;
    int i = blockIdx.x * SCAN_BLK + tid;
    int v = (i < NN) ? g_cnt_dst[i] : 0;
    s[tid] = v;
    __syncthreads();
    for (int o = 1; o < SCAN_BLK; o <<= 1) {
        int t = (tid >= o) ? s[tid - o] : 0;
        __syncthreads();
        s[tid] += t;
        __syncthreads();
    }
    if (i < NN) g_off[i] = s[tid] - v;                 // block-local exclusive
    if (tid == SCAN_BLK - 1) g_bsum[blockIdx.x] = s[tid];
}

__global__ void k_scan2() {
    __shared__ int s[SCAN_BLK];
    int tid = threadIdx.x;
    int v = (tid < NSCAN) ? g_bsum[tid] : 0;
    s[tid] = v;
    __syncthreads();
    for (int o = 1; o < SCAN_BLK; o <<= 1) {
        int t = (tid >= o) ? s[tid - o] : 0;
        __syncthreads();
        s[tid] += t;
        __syncthreads();
    }
    if (tid < NSCAN) g_bsum[tid] = s[tid] - v;         // exclusive block sums
}

__global__ void k_scan3() {
    int i = blockIdx.x * SCAN_BLK + threadIdx.x;
    if (i >= NN) return;
    int o = g_off[i] + g_bsum[blockIdx.x];
    g_off[i] = o;
    g_cur[i] = o;
}

// ---------------------------------------------------------------------------
// CSR fill: csr[pos(dst)] = src
// ---------------------------------------------------------------------------
__global__ void k_fill() {
    int e = blockIdx.x * blockDim.x + threadIdx.x;
    if (e >= NE) return;
    int s = g_idx[e];
    int d = g_idx[NE + e];
    int pos = atomicAdd(&g_cur[d], 1);
    g_csr[pos] = s;
}

// ---------------------------------------------------------------------------
// gemm1: x1 = (feat * ns[:,None]) @ W1   [NN,1433] x [1433,16]
// Block = 8 warps = 256 rows; grid = ceil(NN/256) = 391 blocks.
// Per k-tile: each warp stages its 32x32 feature sub-tile (pad 33), block
// cooperatively stages the 32x16 W tile in smem. Inner kk loop fully
// branch-free. Row tail (last block): feature row reads clamped to NN-1
// (keeps coalescing, values unused), stores guarded by myrow < NN.
// K tail: feature tile zero-filled, W row clamped (0 * finite = 0).
// 16 output cols packed into 8 f32x2 accumulators (FFMA2).
// ---------------------------------------------------------------------------
__global__ void __launch_bounds__(256) k_gemm1(const float* __restrict__ feat,
                                               const float* __restrict__ W1) {
    __shared__ float tile[8][32][33];
    __shared__ float sW[32][16];
    const int tid  = threadIdx.x;
    const int warp = tid >> 5;
    const int lane = tid & 31;
    const int r0 = (blockIdx.x * 8 + warp) * 32;

    unsigned long long acc[8];
#pragma unroll
    for (int j = 0; j < 8; j++) acc[j] = 0ULL;   // (0.f, 0.f)

    float (*t)[33] = tile[warp];

    for (int k0 = 0; k0 < INF; k0 += 32) {
        const int k = k0 + lane;
        const bool kok = (k < INF);
        // stage feature sub-tile (coalesced 128B per row; row clamped for tail)
#pragma unroll 8
        for (int rr = 0; rr < 32; rr++) {
            const int r = min(r0 + rr, NN - 1);
            t[rr][lane] = kok ? feat[(size_t)r * INF + k] : 0.f;
        }
        // stage W tile: 32 rows x 16 cols = 512 floats, 256 threads x 2
        {
            const int i0 = tid;                 // [0,256)
            const int i1 = tid + 256;           // [256,512)
            const int kr0 = i0 >> 4, kc0 = i0 & 15;
            const int kr1 = i1 >> 4, kc1 = i1 & 15;
            sW[kr0][kc0] = W1[(size_t)min(k0 + kr0, INF - 1) * 16 + kc0];
            sW[kr1][kc1] = W1[(size_t)min(k0 + kr1, INF - 1) * 16 + kc1];
        }
        __syncthreads();

#pragma unroll 8
        for (int kk = 0; kk < 32; kk++) {
            const float f = t[lane][kk];       // conflict-free: bank=(lane+kk)%32
            unsigned long long ff;
            asm("mov.b64 %0, {%1, %1};" : "=l"(ff) : "f"(f));
            const unsigned long long* wr = (const unsigned long long*)sW[kk]; // broadcast
            const unsigned long long w0 = wr[0], w1 = wr[1], w2 = wr[2], w3 = wr[3];
            const unsigned long long w4 = wr[4], w5 = wr[5], w6 = wr[6], w7 = wr[7];
            asm("fma.rn.f32x2 %0, %1, %2, %0;" : "+l"(acc[0]) : "l"(ff), "l"(w0));
            asm("fma.rn.f32x2 %0, %1, %2, %0;" : "+l"(acc[1]) : "l"(ff), "l"(w1));
            asm("fma.rn.f32x2 %0, %1, %2, %0;" : "+l"(acc[2]) : "l"(ff), "l"(w2));
            asm("fma.rn.f32x2 %0, %1, %2, %0;" : "+l"(acc[3]) : "l"(ff), "l"(w3));
            asm("fma.rn.f32x2 %0, %1, %2, %0;" : "+l"(acc[4]) : "l"(ff), "l"(w4));
            asm("fma.rn.f32x2 %0, %1, %2, %0;" : "+l"(acc[5]) : "l"(ff), "l"(w5));
            asm("fma.rn.f32x2 %0, %1, %2, %0;" : "+l"(acc[6]) : "l"(ff), "l"(w6));
            asm("fma.rn.f32x2 %0, %1, %2, %0;" : "+l"(acc[7]) : "l"(ff), "l"(w7));
        }
        __syncthreads();
    }

    const int myrow = r0 + lane;
    if (myrow < NN) {
        const float s = g_ns[myrow];
        float o[16];
#pragma unroll
        for (int j = 0; j < 8; j++) {
            float lo, hi;
            asm("mov.b64 {%0, %1}, %2;" : "=f"(lo), "=f"(hi) : "l"(acc[j]));
            o[2 * j]     = lo * s;
            o[2 * j + 1] = hi * s;
        }
        float4* op = (float4*)(g_x1 + (size_t)myrow * 16);
#pragma unroll
        for (int c = 0; c < 4; c++)
            op[c] = make_float4(o[4 * c], o[4 * c + 1], o[4 * c + 2], o[4 * c + 3]);
    }
}

// ---------------------------------------------------------------------------
// gather1: m1[n] = sum over incoming edges of x1[src]; 16 lanes per node
// ---------------------------------------------------------------------------
__global__ void __launch_bounds__(256) k_gather1() {
    int t = blockIdx.x * blockDim.x + threadIdx.x;
    int node = t >> 4;
    int j = t & 15;
    if (node >= NN) return;
    int beg = g_off[node];
    int end = beg + g_cnt_dst[node];
    float acc = 0.f;
#pragma unroll 4
    for (int e = beg; e < end; e++) {
        int s = g_csr[e];                          // broadcast across 16 lanes
        acc += g_x1[(size_t)s * 16 + j];
    }
    g_m1[(size_t)node * 16 + j] = acc;
}

// ---------------------------------------------------------------------------
// layer2: h = relu(m1*nd + b1);  x2 = (h*ns) @ W2  (pad col 7 = 0)
// ---------------------------------------------------------------------------
__global__ void __launch_bounds__(256) k_layer2(const float* __restrict__ b1,
                                                const float* __restrict__ W2) {
    __shared__ float sW[16 * 7];
    __shared__ float sb1[16];
    const int tid = threadIdx.x;
    if (tid < 112) sW[tid] = W2[tid];
    if (tid < 16)  sb1[tid] = b1[tid];
    __syncthreads();

    const int r = blockIdx.x * blockDim.x + tid;
    if (r >= NN) return;
    const float nd = g_nd[r];
    const float ns = g_ns[r];

    float h[16];
    const float4* m = (const float4*)(g_m1 + (size_t)r * 16);
#pragma unroll
    for (int c = 0; c < 4; c++) {
        const float4 v = m[c];
        h[4 * c + 0] = fmaxf(fmaf(v.x, nd, sb1[4 * c + 0]), 0.f) * ns;
        h[4 * c + 1] = fmaxf(fmaf(v.y, nd, sb1[4 * c + 1]), 0.f) * ns;
        h[4 * c + 2] = fmaxf(fmaf(v.z, nd, sb1[4 * c + 2]), 0.f) * ns;
        h[4 * c + 3] = fmaxf(fmaf(v.w, nd, sb1[4 * c + 3]), 0.f) * ns;
    }

    float* xo = g_x2 + (size_t)r * 8;
#pragma unroll
    for (int j2 = 0; j2 < 7; j2++) {
        float o = 0.f;
#pragma unroll
        for (int j = 0; j < 16; j++) o = fmaf(h[j], sW[j * 7 + j2], o);
        xo[j2] = o;
    }
    xo[7] = 0.f;
}

// ---------------------------------------------------------------------------
// gather2 + epilogue: out[n,:7] = (sum x2[src]) * nd + b2 ; 8 lanes per node
// ---------------------------------------------------------------------------
__global__ void __launch_bounds__(256) k_gather2(float* __restrict__ out,
                                                 const float* __restrict__ b2) {
    int t = blockIdx.x * blockDim.x + threadIdx.x;
    int node = t >> 3;
    int j = t & 7;
    if (node >= NN) return;
    int beg = g_off[node];
    int end = beg + g_cnt_dst[node];
    float acc = 0.f;
#pragma unroll 4
    for (int e = beg; e < end; e++) {
        int s = g_csr[e];                          // broadcast across 8 lanes
        acc += g_x2[(size_t)s * 8 + j];
    }
    if (j < 7)
        out[(size_t)node * 7 + j] = fmaf(acc, g_nd[node], __ldg(b2 + j));
}

// ---------------------------------------------------------------------------
extern "C" void kernel_launch(void* const* d_in, const int* in_sizes, int n_in,
                              void* d_out, int out_size) {
    const float* feat = (const float*)d_in[0];
    const void*  ei   = d_in[1];
    const float* W1   = (const float*)d_in[2];
    const float* b1   = (const float*)d_in[3];
    const float* W2   = (const float*)d_in[4];
    const float* b2   = (const float*)d_in[5];
    float*       out  = (float*)d_out;

    k_detect<<<1, 32>>>((const unsigned int*)ei);
    k_convert<<<(2 * NE + 255) / 256, 256>>>(ei);
    k_zero<<<(NN + 255) / 256, 256>>>();
    k_count<<<(NE + 255) / 256, 256>>>();
    k_norm<<<(NN + 255) / 256, 256>>>();
    k_scan1<<<NSCAN, SCAN_BLK>>>();
    k_scan2<<<1, SCAN_BLK>>>();
    k_scan3<<<NSCAN, SCAN_BLK>>>();
    k_fill<<<(NE + 255) / 256, 256>>>();
    k_gemm1<<<(NN + 255) / 256, 256>>>(feat, W1);
    k_gather1<<<(NN * 16 + 255) / 256, 256>>>();
    k_layer2<<<(NN + 255) / 256, 256>>>(b1, W2);
    k_gather2<<<(NN * 8 + 255) / 256, 256>>>(out, b2);
}

// round 9
// speedup vs baseline: 2.1589x; 1.1498x over previous
#include <cuda_runtime.h>
#include <cstdint>

#define NN   100000
#define NE   3200000
#define INF  1433
#define HID  16
#define OUTF 7
#define SCAN_BLK 512
#define NSCAN ((NN + SCAN_BLK - 1) / SCAN_BLK)   // 196

// ---- scratch (device globals: allocation-free) ----
__device__ int   g_idx64;               // 1 if edge_index is int64, 0 if int32
__device__ int   g_idx[2 * NE];         // densified edge indices: [src | dst]
__device__ int   g_csr[NE];             // src ids sorted by dst
__device__ int   g_cnt_src[NN];         // out-degree
__device__ int   g_cnt_dst[NN];         // in-degree
__device__ int   g_off[NN];             // CSR row offsets (by dst)
__device__ int   g_cur[NN];             // fill cursors
__device__ int   g_bsum[NSCAN];         // scan block sums
__device__ float g_ns[NN];
__device__ float g_nd[NN];
__device__ float g_x1[(size_t)NN * HID];   // RAW feat@W1 (ns applied in gather1)
__device__ float g_m1[(size_t)NN * HID];   // gathered layer-1 messages
__device__ float g_x2[(size_t)NN * 8];     // (relu(h)*ns)@W2, padded to 8

// ---- streams/events for capture-fork (created before harness checkpoints) ----
struct HxInit {
    cudaStream_t s2;
    cudaEvent_t  e0, e1;
    HxInit() {
        cudaStreamCreateWithFlags(&s2, cudaStreamNonBlocking);
        cudaEventCreateWithFlags(&e0, cudaEventDisableTiming);
        cudaEventCreateWithFlags(&e1, cudaEventDisableTiming);
    }
};
static HxInit g_hx;

// ---------------------------------------------------------------------------
// dtype detect: odd 32-bit words all-zero <=> int64 with small values
// ---------------------------------------------------------------------------
__global__ void k_detect(const unsigned int* __restrict__ ei_words) {
    __shared__ unsigned int acc;
    if (threadIdx.x == 0) acc = 0u;
    __syncthreads();
    unsigned int v = ei_words[2 * threadIdx.x + 1];
    atomicOr(&acc, v);
    __syncthreads();
    if (threadIdx.x == 0) g_idx64 = (acc == 0u) ? 1 : 0;
}

__global__ void k_zero() {
    int i = blockIdx.x * blockDim.x + threadIdx.x;
    if (i < NN) { g_cnt_src[i] = 0; g_cnt_dst[i] = 0; }
}

// ---------------------------------------------------------------------------
// fused convert + degree count: one pass over edge_index
// ---------------------------------------------------------------------------
__global__ void k_convcnt(const void* __restrict__ ei) {
    int e = blockIdx.x * blockDim.x + threadIdx.x;
    if (e >= NE) return;
    int s, d;
    if (g_idx64) {
        s = (int)((const long long*)ei)[e];
        d = (int)((const long long*)ei)[(size_t)NE + e];
    } else {
        s = ((const int*)ei)[e];
        d = ((const int*)ei)[NE + e];
    }
    g_idx[e] = s;
    g_idx[NE + e] = d;
    atomicAdd(&g_cnt_src[s], 1);
    atomicAdd(&g_cnt_dst[d], 1);
}

__global__ void k_norm() {
    int i = blockIdx.x * blockDim.x + threadIdx.x;
    if (i >= NN) return;
    g_ns[i] = rsqrtf(fmaxf((float)g_cnt_src[i], 1.0f));
    g_nd[i] = rsqrtf(fmaxf((float)g_cnt_dst[i], 1.0f));
}

// ---------------------------------------------------------------------------
// exclusive scan of g_cnt_dst -> g_off  (3 kernels)
// ---------------------------------------------------------------------------
__global__ void k_scan1() {
    __shared__ int s[SCAN_BLK];
    int tid = threadIdx.x;
    int i = blockIdx.x * SCAN_BLK + tid;
    int v = (i < NN) ? g_cnt_dst[i] : 0;
    s[tid] = v;
    __syncthreads();
    for (int o = 1; o < SCAN_BLK; o <<= 1) {
        int t = (tid >= o) ? s[tid - o] : 0;
        __syncthreads();
        s[tid] += t;
        __syncthreads();
    }
    if (i < NN) g_off[i] = s[tid] - v;                 // block-local exclusive
    if (tid == SCAN_BLK - 1) g_bsum[blockIdx.x] = s[tid];
}

__global__ void k_scan2() {
    __shared__ int s[SCAN_BLK];
    int tid = threadIdx.x;
    int v = (tid < NSCAN) ? g_bsum[tid] : 0;
    s[tid] = v;
    __syncthreads();
    for (int o = 1; o < SCAN_BLK; o <<= 1) {
        int t = (tid >= o) ? s[tid - o] : 0;
        __syncthreads();
        s[tid] += t;
        __syncthreads();
    }
    if (tid < NSCAN) g_bsum[tid] = s[tid] - v;         // exclusive block sums
}

__global__ void k_scan3() {
    int i = blockIdx.x * SCAN_BLK + threadIdx.x;
    if (i >= NN) return;
    int o = g_off[i] + g_bsum[blockIdx.x];
    g_off[i] = o;
    g_cur[i] = o;
}

// ---------------------------------------------------------------------------
// CSR fill: csr[pos(dst)] = src
// ---------------------------------------------------------------------------
__global__ void k_fill() {
    int e = blockIdx.x * blockDim.x + threadIdx.x;
    if (e >= NE) return;
    int s = g_idx[e];
    int d = g_idx[NE + e];
    int pos = atomicAdd(&g_cur[d], 1);
    g_csr[pos] = s;
}

// ---------------------------------------------------------------------------
// gemm1: x1_raw = feat @ W1   [NN,1433] x [1433,16]   (no ns — independent
// of the edge pipeline, runs on a forked stream concurrent with CSR build)
// Block = 4 warps = 128 rows; grid = 782 (single resident wave, ~32 warps/SM).
// Inner kk loop branch-free; row tail clamped, K tail zero-filled.
// 16 output cols packed into 8 f32x2 accumulators (FFMA2).
// ---------------------------------------------------------------------------
__global__ void __launch_bounds__(128) k_gemm1(const float* __restrict__ feat,
                                               const float* __restrict__ W1) {
    __shared__ float tile[4][32][33];
    __shared__ float sW[32][16];
    const int tid  = threadIdx.x;
    const int warp = tid >> 5;
    const int lane = tid & 31;
    const int r0 = (blockIdx.x * 4 + warp) * 32;

    unsigned long long acc[8];
#pragma unroll
    for (int j = 0; j < 8; j++) acc[j] = 0ULL;   // (0.f, 0.f)

    float (*t)[33] = tile[warp];

    for (int k0 = 0; k0 < INF; k0 += 32) {
        const int k = k0 + lane;
        const bool kok = (k < INF);
        // stage feature sub-tile (coalesced 128B per row; row clamped for tail)
#pragma unroll 8
        for (int rr = 0; rr < 32; rr++) {
            const int r = min(r0 + rr, NN - 1);
            t[rr][lane] = kok ? feat[(size_t)r * INF + k] : 0.f;
        }
        // stage W tile: 32x16 = 512 floats, 128 threads x 4
        {
#pragma unroll
            for (int q = 0; q < 4; q++) {
                const int i = tid + q * 128;
                const int kr = i >> 4, kc = i & 15;
                sW[kr][kc] = W1[(size_t)min(k0 + kr, INF - 1) * 16 + kc];
            }
        }
        __syncthreads();

#pragma unroll 8
        for (int kk = 0; kk < 32; kk++) {
            const float f = t[lane][kk];       // conflict-free: bank=(lane+kk)%32
            unsigned long long ff;
            asm("mov.b64 %0, {%1, %1};" : "=l"(ff) : "f"(f));
            const unsigned long long* wr = (const unsigned long long*)sW[kk]; // broadcast
            const unsigned long long w0 = wr[0], w1 = wr[1], w2 = wr[2], w3 = wr[3];
            const unsigned long long w4 = wr[4], w5 = wr[5], w6 = wr[6], w7 = wr[7];
            asm("fma.rn.f32x2 %0, %1, %2, %0;" : "+l"(acc[0]) : "l"(ff), "l"(w0));
            asm("fma.rn.f32x2 %0, %1, %2, %0;" : "+l"(acc[1]) : "l"(ff), "l"(w1));
            asm("fma.rn.f32x2 %0, %1, %2, %0;" : "+l"(acc[2]) : "l"(ff), "l"(w2));
            asm("fma.rn.f32x2 %0, %1, %2, %0;" : "+l"(acc[3]) : "l"(ff), "l"(w3));
            asm("fma.rn.f32x2 %0, %1, %2, %0;" : "+l"(acc[4]) : "l"(ff), "l"(w4));
            asm("fma.rn.f32x2 %0, %1, %2, %0;" : "+l"(acc[5]) : "l"(ff), "l"(w5));
            asm("fma.rn.f32x2 %0, %1, %2, %0;" : "+l"(acc[6]) : "l"(ff), "l"(w6));
            asm("fma.rn.f32x2 %0, %1, %2, %0;" : "+l"(acc[7]) : "l"(ff), "l"(w7));
        }
        __syncthreads();
    }

    const int myrow = r0 + lane;
    if (myrow < NN) {
        float o[16];
#pragma unroll
        for (int j = 0; j < 8; j++) {
            float lo, hi;
            asm("mov.b64 {%0, %1}, %2;" : "=f"(lo), "=f"(hi) : "l"(acc[j]));
            o[2 * j]     = lo;
            o[2 * j + 1] = hi;
        }
        float4* op = (float4*)(g_x1 + (size_t)myrow * 16);
#pragma unroll
        for (int c = 0; c < 4; c++)
            op[c] = make_float4(o[4 * c], o[4 * c + 1], o[4 * c + 2], o[4 * c + 3]);
    }
}

// ---------------------------------------------------------------------------
// gather1: m1[n] = sum_e ns[src] * x1_raw[src]; 16 lanes per node
// ---------------------------------------------------------------------------
__global__ void __launch_bounds__(256) k_gather1() {
    int t = blockIdx.x * blockDim.x + threadIdx.x;
    int node = t >> 4;
    int j = t & 15;
    if (node >= NN) return;
    int beg = g_off[node];
    int end = beg + g_cnt_dst[node];
    float acc = 0.f;
#pragma unroll 4
    for (int e = beg; e < end; e++) {
        int s = g_csr[e];                          // broadcast across 16 lanes
        float nsv = g_ns[s];                       // broadcast
        acc = fmaf(g_x1[(size_t)s * 16 + j], nsv, acc);
    }
    g_m1[(size_t)node * 16 + j] = acc;
}

// ---------------------------------------------------------------------------
// layer2: h = relu(m1*nd + b1);  x2 = (h*ns) @ W2  (pad col 7 = 0)
// ---------------------------------------------------------------------------
__global__ void __launch_bounds__(256) k_layer2(const float* __restrict__ b1,
                                                const float* __restrict__ W2) {
    __shared__ float sW[16 * 7];
    __shared__ float sb1[16];
    const int tid = threadIdx.x;
    if (tid < 112) sW[tid] = W2[tid];
    if (tid < 16)  sb1[tid] = b1[tid];
    __syncthreads();

    const int r = blockIdx.x * blockDim.x + tid;
    if (r >= NN) return;
    const float nd = g_nd[r];
    const float ns = g_ns[r];

    float h[16];
    const float4* m = (const float4*)(g_m1 + (size_t)r * 16);
#pragma unroll
    for (int c = 0; c < 4; c++) {
        const float4 v = m[c];
        h[4 * c + 0] = fmaxf(fmaf(v.x, nd, sb1[4 * c + 0]), 0.f) * ns;
        h[4 * c + 1] = fmaxf(fmaf(v.y, nd, sb1[4 * c + 1]), 0.f) * ns;
        h[4 * c + 2] = fmaxf(fmaf(v.z, nd, sb1[4 * c + 2]), 0.f) * ns;
        h[4 * c + 3] = fmaxf(fmaf(v.w, nd, sb1[4 * c + 3]), 0.f) * ns;
    }

    float* xo = g_x2 + (size_t)r * 8;
#pragma unroll
    for (int j2 = 0; j2 < 7; j2++) {
        float o = 0.f;
#pragma unroll
        for (int j = 0; j < 16; j++) o = fmaf(h[j], sW[j * 7 + j2], o);
        xo[j2] = o;
    }
    xo[7] = 0.f;
}

// ---------------------------------------------------------------------------
// gather2 + epilogue: out[n,:7] = (sum x2[src]) * nd + b2 ; 8 lanes per node
// ---------------------------------------------------------------------------
__global__ void __launch_bounds__(256) k_gather2(float* __restrict__ out,
                                                 const float* __restrict__ b2) {
    int t = blockIdx.x * blockDim.x + threadIdx.x;
    int node = t >> 3;
    int j = t & 7;
    if (node >= NN) return;
    int beg = g_off[node];
    int end = beg + g_cnt_dst[node];
    float acc = 0.f;
#pragma unroll 4
    for (int e = beg; e < end; e++) {
        int s = g_csr[e];                          // broadcast across 8 lanes
        acc += g_x2[(size_t)s * 8 + j];
    }
    if (j < 7)
        out[(size_t)node * 7 + j] = fmaf(acc, g_nd[node], __ldg(b2 + j));
}

// ---------------------------------------------------------------------------
extern "C" void kernel_launch(void* const* d_in, const int* in_sizes, int n_in,
                              void* d_out, int out_size) {
    const float* feat = (const float*)d_in[0];
    const void*  ei   = d_in[1];
    const float* W1   = (const float*)d_in[2];
    const float* b1   = (const float*)d_in[3];
    const float* W2   = (const float*)d_in[4];
    const float* b2   = (const float*)d_in[5];
    float*       out  = (float*)d_out;

    // fork: gemm1 (independent of edges) runs concurrent with CSR build
    cudaEventRecord(g_hx.e0, 0);
    cudaStreamWaitEvent(g_hx.s2, g_hx.e0, 0);
    k_gemm1<<<(NN + 127) / 128, 128, 0, g_hx.s2>>>(feat, W1);
    cudaEventRecord(g_hx.e1, g_hx.s2);

    // main stream: CSR build
    k_detect<<<1, 32>>>((const unsigned int*)ei);
    k_zero<<<(NN + 255) / 256, 256>>>();
    k_convcnt<<<(NE + 255) / 256, 256>>>(ei);
    k_norm<<<(NN + 255) / 256, 256>>>();
    k_scan1<<<NSCAN, SCAN_BLK>>>();
    k_scan2<<<1, SCAN_BLK>>>();
    k_scan3<<<NSCAN, SCAN_BLK>>>();
    k_fill<<<(NE + 255) / 256, 256>>>();

    // join: gather needs x1 + CSR
    cudaStreamWaitEvent(0, g_hx.e1, 0);
    k_gather1<<<(NN * 16 + 255) / 256, 256>>>();
    k_layer2<<<(NN + 255) / 256, 256>>>(b1, W2);
    k_gather2<<<(NN * 8 + 255) / 256, 256>>>(out, b2);
}